// round 15
// baseline (speedup 1.0000x reference)
#include <cuda_runtime.h>
#include <cstdint>

#define Dd 64
#define Hh 128
#define Ww 128
#define HW (Hh*Ww)
#define NN (Dd*Hh*Ww)

// ---------------- scratch (device globals: alloc-free, capture-safe) ----------
__device__ float g_t[NN];
__device__ float g_z[NN];
__device__ float g_p[NN];
__device__ float g_q[NN];
__device__ float g_s[NN];
__device__ float g_zp[NN];
// bf16 intermediate h2, DOUBLE-BUFFERED so conv3(i) can overlap conv12(i+1)
__device__ uint32_t g_h2b[2][8*NN];
// prepped bf16 weight fragments (constant across cascades)
__device__ uint4  g_w2f4[4*864];    // [br][tap 27][nt 2][lane 32] uint2 pairs
__device__ uint4  g_w3f4[4*432];    // [br][tap 27][lane 32] uint2 pairs
__device__ uint2  g_w1f[4*128];     // [br][lane 32][ks 2][nt 2]

// ---------------- bf16 / mma.sync helpers (family-safe PTX) ---------------------
static __device__ __forceinline__ uint32_t smem_u32(const void* p){
    uint32_t a;
    asm("{ .reg .u64 t; cvta.to.shared.u64 t, %1; cvt.u32.u64 %0, t; }" : "=r"(a) : "l"(p));
    return a;
}
static __device__ __forceinline__ uint32_t bf16x2(float lo, float hi){
    uint32_t r;
    asm("cvt.rn.bf16x2.f32 %0, %1, %2;" : "=r"(r) : "f"(hi), "f"(lo));
    return r;
}
static __device__ __forceinline__ void lds_v2(uint32_t addr, uint32_t &x, uint32_t &y){
    asm volatile("ld.shared.v2.u32 {%0,%1}, [%2];" : "=r"(x), "=r"(y) : "r"(addr));
}
static __device__ __forceinline__ float lds_f32(uint32_t addr){
    float v;
    asm volatile("ld.shared.f32 %0, [%1];" : "=f"(v) : "r"(addr));
    return v;
}
static __device__ __forceinline__ void sts_u32(uint32_t addr, uint32_t v){
    asm volatile("st.shared.u32 [%0], %1;" :: "r"(addr), "r"(v));
}
static __device__ __forceinline__ void mma_bf16(float* c, uint32_t a0, uint32_t a1,
                                                uint32_t a2, uint32_t a3,
                                                uint32_t b0, uint32_t b1){
    asm volatile(
        "mma.sync.aligned.m16n8k16.row.col.f32.bf16.bf16.f32 "
        "{%0,%1,%2,%3}, {%4,%5,%6,%7}, {%8,%9}, {%0,%1,%2,%3};"
        : "+f"(c[0]), "+f"(c[1]), "+f"(c[2]), "+f"(c[3])
        : "r"(a0), "r"(a1), "r"(a2), "r"(a3), "r"(b0), "r"(b1));
}

// x = fdiff(z, axis) on the fly (0:W, 1:H, 2:D, 3:identity)
template<int MODE>
static __device__ __forceinline__ float getx(int d, int h, int w){
    if (d < 0 || d >= Dd || h < 0 || h >= Hh || w < 0 || w >= Ww) return 0.f;
    int idx = (d*Hh + h)*Ww + w;
    if (MODE == 0) return (w < Ww-1) ? g_z[idx+1]  - g_z[idx] : 0.f;
    if (MODE == 1) return (h < Hh-1) ? g_z[idx+Ww] - g_z[idx] : 0.f;
    if (MODE == 2) return (d < Dd-1) ? g_z[idx+HW] - g_z[idx] : 0.f;
    return g_z[idx];
}

// ---------------- init ------------------------------------------------------------
__global__ void k_init(const float* __restrict__ img, float* __restrict__ outp){
    int idx = blockIdx.x*256 + threadIdx.x;
    float v = img[idx];
    g_t[idx] = v;
    outp[idx] = v;
    g_p[idx] = 0.f; g_q[idx] = 0.f; g_s[idx] = 0.f;
}

// ---------------- weight prep: f32 -> bf16 fragment layouts ----------------------
__global__ void k_wprep(const float* __restrict__ w1,
                        const float* __restrict__ w2,
                        const float* __restrict__ w3){
    const int br = blockIdx.x;
    const int tid = threadIdx.x;
    uint32_t* w2f = reinterpret_cast<uint32_t*>(g_w2f4) + br*3456;
    for (int i = tid; i < 1728; i += 256){
        int l = i & 31, nt = (i >> 5) & 1, tap = i >> 6;
        int lt = l & 3, lg = l >> 2;
        const float* wp = w2 + br*6912 + ((nt*8 + lg)*16)*27 + tap;
        uint32_t base = (uint32_t)(tap*512 + nt*256 + l*8) >> 2;
        w2f[base + 0] = bf16x2(wp[(2*lt  )*27], wp[(2*lt+1)*27]);
        w2f[base + 1] = bf16x2(wp[(2*lt+8)*27], wp[(2*lt+9)*27]);
    }
    uint32_t* w3f = reinterpret_cast<uint32_t*>(g_w3f4) + br*1728;
    for (int i = tid; i < 864; i += 256){
        int l = i & 31, tap = i >> 5;
        int lt = l & 3, lg = l >> 2;
        uint32_t v0 = 0u, v1 = 0u;
        if (lg == 0){
            const float* wp = w3 + br*432;
            v0 = bf16x2(wp[(2*lt  )*27 + tap], wp[(2*lt+1)*27 + tap]);
            v1 = bf16x2(wp[(2*lt+8)*27 + tap], wp[(2*lt+9)*27 + tap]);
        }
        uint32_t base = (uint32_t)(tap*256 + l*8) >> 2;
        w3f[base + 0] = v0;
        w3f[base + 1] = v1;
    }
    if (tid < 128){
        int l = tid & 31, ksnt = tid >> 5;
        int ks = ksnt >> 1, nt = ksnt & 1;
        int t = l & 3, g = l >> 2;
        const float* wp = w1 + br*432 + (nt*8 + g)*27;
        int k0 = ks*16 + 2*t;
        float f0 = (k0   < 27) ? wp[k0  ] : 0.f;
        float f1 = (k0+1 < 27) ? wp[k0+1] : 0.f;
        float f8 = (k0+8 < 27) ? wp[k0+8] : 0.f;
        float f9 = (k0+9 < 27) ? wp[k0+9] : 0.f;
        g_w1f[br*128 + l*4 + ks*2 + nt] = make_uint2(bf16x2(f0,f1), bf16x2(f8,f9));
    }
}

// ---------------- fused column kernels --------------------------------------------
__global__ void k_sumz(const float* __restrict__ sino){
    __shared__ float red[256];
    __shared__ float corr[64];
    const int tid = threadIdx.x;
    const int j = blockIdx.x*64 + (tid & 63);
    const int part = tid >> 6;
    const int dlo = part*16;
    float sum = 0.f;
    #pragma unroll
    for (int d = dlo; d < dlo+16; d++) sum += g_t[d*HW + j];
    red[tid] = sum;
    __syncthreads();
    if (part == 0){
        float s4 = red[tid] + red[tid+64] + red[tid+128] + red[tid+192];
        corr[tid] = (sino[j] - s4) * (1.f/64.f);
    }
    __syncthreads();
    float cv = corr[tid & 63];
    #pragma unroll
    for (int d = dlo; d < dlo+16; d++){
        int idx = d*HW + j;
        g_z[idx] = g_t[idx] + cv;
    }
}

__global__ void k_updz(float* __restrict__ outp, const float* __restrict__ sino){
    __shared__ float red[256];
    __shared__ float corr[64];
    const int tid = threadIdx.x;
    const int j = blockIdx.x*64 + (tid & 63);
    const int part = tid >> 6;
    const int dlo = part*16;
    const int w = j & (Ww-1);
    const int h = j >> 7;
    float sprev = (dlo > 0) ? g_s[(dlo-1)*HW + j] : 0.f;
    float sum = 0.f;
    #pragma unroll
    for (int d = dlo; d < dlo+16; d++){
        int idx = d*HW + j;
        float pv = g_p[idx], pm = (w > 0) ? g_p[idx-1] : 0.f;
        float fa = (w==Ww-1) ? pm : (pm - pv);
        float qv = g_q[idx], qm = (h > 0) ? g_q[idx-Ww] : 0.f;
        float fb = (h==Hh-1) ? qm : (qm - qv);
        float sv = g_s[idx];
        float fc = (d==Dd-1) ? sprev : (((d>0) ? sprev : 0.f) - sv);
        sprev = sv;
        float tn = fa + fb + fc + g_zp[idx];
        g_t[idx] = tn;
        outp[idx] = tn;
        sum += tn;
    }
    red[tid] = sum;
    __syncthreads();
    if (part == 0){
        float s4 = red[tid] + red[tid+64] + red[tid+128] + red[tid+192];
        corr[tid] = (sino[j] - s4) * (1.f/64.f);
    }
    __syncthreads();
    float cv = corr[tid & 63];
    #pragma unroll
    for (int d = dlo; d < dlo+16; d++){
        int idx = d*HW + j;
        g_z[idx] = g_t[idx] + cv;
    }
}

// ================= fused conv1+conv2 body =====================================
#define A_BYTES   (108*320)                // 34560
#define B2_OFF    A_BYTES
#define XT_OFF    (B2_OFF + 27*512)        // 48384
#define LUT_OFF   (XT_OFF + 1920*4)        // 56064
#define CV12_SMEM (LUT_OFF + 1080*8)       // 64704
#define B3_OFF    A_BYTES

template<int MODE>
static __device__ __forceinline__ void conv12_body(char* smem, int tid,
                                                   int w0, int h0, int d0,
                                                   const float* b1a,
                                                   const float* b2a,
                                                   uint32_t* __restrict__ h2out){
    float* xs = reinterpret_cast<float*>(smem + XT_OFF);
    uint2* lut = reinterpret_cast<uint2*>(smem + LUT_OFF);
    const int wid = tid >> 5;
    const int lane = tid & 31;
    const int t = lane & 3, g = lane >> 2;
    const float* b2 = b2a + MODE*16;
    const uint32_t sb_ = smem_u32(smem);
    const uint32_t xu  = sb_ + XT_OFF;

    for (int i = tid; i < 1920; i += 256){
        int w = i % 12; int r = i / 12;
        int h = r % 20; int dz = r / 20;
        xs[i] = getx<MODE>(d0-2+dz, h0-2+h, w0-2+w);
    }
    {
        const uint4* wsrc = g_w2f4 + MODE*864;
        uint4* wdst = reinterpret_cast<uint4*>(smem + B2_OFF);
        for (int i = tid; i < 864; i += 256) wdst[i] = wsrc[i];
    }
    for (int r = tid; r < 1080; r += 256){
        int dz = r/180, rem = r - dz*180;
        int h = rem/10, w = rem - h*10;
        int dg = d0-1+dz, hg = h0-1+h, wg = w0-1+w;
        bool in = (dg>=0) & (dg<Dd) & (hg>=0) & (hg<Hh) & (wg>=0) & (wg<Ww);
        uint32_t xoff = (uint32_t)((dz*240 + h*12 + w)*4);
        uint32_t aoff = (uint32_t)((dz*18 + h)*320 + w*32) | (in ? 1u : 0u);
        lut[r] = make_uint2(xoff, aoff);
    }
    __syncthreads();

    // conv1 phase
    {
        uint2 B1[2][2];
        #pragma unroll
        for (int ks=0; ks<2; ks++)
            #pragma unroll
            for (int nt=0; nt<2; nt++)
                B1[ks][nt] = g_w1f[MODE*128 + lane*4 + ks*2 + nt];
        float blv[2], bhv[2];
        #pragma unroll
        for (int nt=0; nt<2; nt++){
            blv[nt] = b1a[MODE*16 + nt*8 + 2*t];
            bhv[nt] = b1a[MODE*16 + nt*8 + 2*t + 1];
        }
        uint32_t offb[8]; bool vvk[8];
        #pragma unroll
        for (int j=0; j<8; j++){
            int k = 2*t + (j&1) + ((j>>1)&1)*8 + (j>>2)*16;
            vvk[j] = (k < 27);
            int kk = vvk[j] ? k : 0;
            int dd = kk/9, rem = kk - dd*9;
            int dh = rem/3, dw = rem - dh*3;
            offb[j] = (uint32_t)((dd*240 + dh*12 + dw)*4);
        }
        #pragma unroll 1
        for (int it = 0; it < 9; it++){
            int m = wid + it*8;
            if (m >= 68) break;
            int rA = m*16 + g, rB = rA + 8;
            bool vA = rA < 1080, vB = rB < 1080;
            uint2 LA = lut[vA ? rA : 0];
            uint2 LB = lut[vB ? rB : 0];
            uint32_t aAx = xu + LA.x, aBx = xu + LB.x;
            bool inA = (LA.y & 1u), inB = (LB.y & 1u);
            uint32_t sA = sb_ + (LA.y & ~1u), sBs = sb_ + (LB.y & ~1u);
            float x0[8], x1[8];
            #pragma unroll
            for (int j=0; j<8; j++){
                x0[j] = vvk[j] ? lds_f32(aAx + offb[j]) : 0.f;
                x1[j] = vvk[j] ? lds_f32(aBx + offb[j]) : 0.f;
            }
            uint32_t a0 = bf16x2(x0[0],x0[1]), a1 = bf16x2(x1[0],x1[1]);
            uint32_t a2 = bf16x2(x0[2],x0[3]), a3 = bf16x2(x1[2],x1[3]);
            uint32_t c0 = bf16x2(x0[4],x0[5]), c1 = bf16x2(x1[4],x1[5]);
            uint32_t c2 = bf16x2(x0[6],x0[7]), c3 = bf16x2(x1[6],x1[7]);
            float acc1[2][4];
            #pragma unroll
            for (int nt=0; nt<2; nt++)
                #pragma unroll
                for (int j=0; j<4; j++) acc1[nt][j] = 0.f;
            #pragma unroll
            for (int nt=0; nt<2; nt++){
                mma_bf16(acc1[nt], a0,a1,a2,a3, B1[0][nt].x, B1[0][nt].y);
                mma_bf16(acc1[nt], c0,c1,c2,c3, B1[1][nt].x, B1[1][nt].y);
            }
            #pragma unroll
            for (int nt=0; nt<2; nt++){
                uint32_t slot = (uint32_t)((t*2 + nt)*4);
                if (vA){
                    uint32_t v = inA ? bf16x2(fmaxf(acc1[nt][0] + blv[nt], 0.f),
                                              fmaxf(acc1[nt][1] + bhv[nt], 0.f)) : 0u;
                    sts_u32(sA + slot, v);
                }
                if (vB){
                    uint32_t v = inB ? bf16x2(fmaxf(acc1[nt][2] + blv[nt], 0.f),
                                              fmaxf(acc1[nt][3] + bhv[nt], 0.f)) : 0u;
                    sts_u32(sBs + slot, v);
                }
            }
        }
    }
    __syncthreads();

    // conv2 mainloop
    float acc[4][8];
    #pragma unroll
    for (int s=0; s<4; s++)
        #pragma unroll
        for (int j=0; j<8; j++) acc[s][j] = 0.f;

    const uint32_t a_base = sb_ + (uint32_t)(2*wid)*320u + (uint32_t)g*32u + (uint32_t)t*8u;
    const uint32_t b_base = sb_ + B2_OFF + (uint32_t)lane*8u;

    #pragma unroll 1
    for (int dh = 0; dh < 3; dh++){
        #pragma unroll
        for (int dw = 0; dw < 3; dw++){
            uint32_t bf[3][2][2];
            #pragma unroll
            for (int dd=0; dd<3; dd++)
                #pragma unroll
                for (int nt=0; nt<2; nt++)
                    lds_v2(b_base + (uint32_t)(dd*9+dh*3+dw)*512u + nt*256u,
                           bf[dd][nt][0], bf[dd][nt][1]);
            uint32_t ab = a_base + (uint32_t)dh*320u + (uint32_t)dw*32u;
            #pragma unroll
            for (int dblk=0; dblk<6; dblk++){
                uint32_t a0,a2,a1,a3;
                lds_v2(ab + (uint32_t)dblk*5760u,        a0, a2);
                lds_v2(ab + (uint32_t)dblk*5760u + 320u, a1, a3);
                #pragma unroll
                for (int dd=0; dd<3; dd++){
                    const int s = dblk - dd;
                    if (s >= 0 && s < 4){
                        mma_bf16(&acc[s][0], a0,a1,a2,a3, bf[dd][0][0], bf[dd][0][1]);
                        mma_bf16(&acc[s][4], a0,a1,a2,a3, bf[dd][1][0], bf[dd][1][1]);
                    }
                }
            }
        }
    }

    #pragma unroll
    for (int nt = 0; nt < 2; nt++){
        float blv = b2[nt*8 + 2*t], bhv = b2[nt*8 + 2*t + 1];
        #pragma unroll
        for (int s = 0; s < 4; s++){
            int pos0 = ((d0+s)*Hh + h0 + 2*wid)*Ww + w0 + g;
            uint32_t v0 = bf16x2(fmaxf(acc[s][nt*4+0] + blv, 0.f),
                                 fmaxf(acc[s][nt*4+1] + bhv, 0.f));
            uint32_t v1 = bf16x2(fmaxf(acc[s][nt*4+2] + blv, 0.f),
                                 fmaxf(acc[s][nt*4+3] + bhv, 0.f));
            h2out[ pos0     *8 + t*2 + nt] = v0;
            h2out[(pos0+Ww) *8 + t*2 + nt] = v1;
        }
    }
}

// ================= conv3 body ==================================================
static __device__ __forceinline__ void stage_A(char* smem, const uint32_t* src,
                                               int tid, int w0, int h0, int d0){
    for (int i = tid; i < 2160; i += 256){
        int half = i & 1;
        int w = (i >> 1) % 10;
        int b = i / 20;
        int d = d0 - 1 + b/18;
        int h = h0 - 1 + b%18;
        int wg = w0 - 1 + w;
        uint4 v = make_uint4(0u,0u,0u,0u);
        if (d >= 0 && d < Dd && h >= 0 && h < Hh && wg >= 0 && wg < Ww)
            v = *reinterpret_cast<const uint4*>(src + (((d*Hh + h)*Ww + wg)*8 + half*4));
        *reinterpret_cast<uint4*>(smem + b*320 + w*32 + half*16) = v;
    }
}

template<int A>
static __device__ __forceinline__ void conv3_body(char* smem, int tid,
                                                  int w0, int h0, int d0,
                                                  const float* b3,
                                                  const float* eta_arr, int c,
                                                  const uint32_t* __restrict__ h2in){
    const int wid = tid >> 5;
    const int lane = tid & 31;
    const int t = lane & 3, g = lane >> 2;

    stage_A(smem, h2in, tid, w0, h0, d0);
    {
        const uint4* wsrc = g_w3f4 + A*432;
        uint4* wdst = reinterpret_cast<uint4*>(smem + B3_OFF);
        for (int i = tid; i < 432; i += 256) wdst[i] = wsrc[i];
    }
    __syncthreads();

    float acc[4][4];
    #pragma unroll
    for (int s=0; s<4; s++)
        #pragma unroll
        for (int j=0; j<4; j++) acc[s][j] = 0.f;

    const uint32_t sb_ = smem_u32(smem);
    const uint32_t a_base = sb_ + (uint32_t)(2*wid)*320u + (uint32_t)g*32u + (uint32_t)t*8u;
    const uint32_t b_base = sb_ + B3_OFF + (uint32_t)lane*8u;

    #pragma unroll 1
    for (int dh = 0; dh < 3; dh++){
        #pragma unroll
        for (int dw = 0; dw < 3; dw++){
            uint32_t bf[3][2];
            #pragma unroll
            for (int dd=0; dd<3; dd++)
                lds_v2(b_base + (uint32_t)(dd*9+dh*3+dw)*256u, bf[dd][0], bf[dd][1]);
            uint32_t ab = a_base + (uint32_t)dh*320u + (uint32_t)dw*32u;
            #pragma unroll
            for (int dblk=0; dblk<6; dblk++){
                uint32_t a0,a2,a1,a3;
                lds_v2(ab + (uint32_t)dblk*5760u,        a0, a2);
                lds_v2(ab + (uint32_t)dblk*5760u + 320u, a1, a3);
                #pragma unroll
                for (int dd=0; dd<3; dd++){
                    const int s = dblk - dd;
                    if (s >= 0 && s < 4)
                        mma_bf16(&acc[s][0], a0,a1,a2,a3, bf[dd][0], bf[dd][1]);
                }
            }
        }
    }

    if (t == 0){
        float* tgt        = (A==0) ? g_p : (A==1) ? g_q : (A==2) ? g_s : g_zp;
        const float* base = (A==3) ? g_t : tgt;
        const float eta = eta_arr[c];
        const float b3v = b3[A];
        #pragma unroll
        for (int s = 0; s < 4; s++){
            #pragma unroll
            for (int hl = 0; hl < 2; hl++){
                int d = d0 + s, h = h0 + 2*wid + hl, w = w0 + g;
                int idx = (d*Hh + h)*Ww + w;
                float nnew = getx<A>(d, h, w) + acc[s][hl*2] + b3v;
                tgt[idx] = (1.f + eta)*base[idx] - eta*nnew;
            }
        }
    }
}

// ================= merged step kernel ==========================================
// D12 && D3: grid.z = 32; z<16 -> conv12(BR1, d0=z*4), z>=16 -> conv3(BR3, d0=(z-16)*4)
// single-op launches use grid.z = 16.
template<int BR1, int BR3, bool D12, bool D3>
__global__ void __launch_bounds__(256,3) k_step(const float* __restrict__ b1,
                                                const float* __restrict__ b2,
                                                const float* __restrict__ b3,
                                                const float* __restrict__ e0,
                                                const float* __restrict__ e1,
                                                const float* __restrict__ e2,
                                                const float* __restrict__ e3,
                                                int c){
    extern __shared__ char smem[];
    const int tid = threadIdx.x;
    const int w0 = blockIdx.x*8, h0 = blockIdx.y*16;
    const int z = blockIdx.z;
    if (D12 && (!D3 || z < 16)){
        conv12_body<BR1>(smem, tid, w0, h0, z*4, b1, b2, &g_h2b[BR1 & 1][0]);
    } else if (D3) {
        int z3 = D12 ? (z - 16) : z;
        const float* eta = (BR3==0) ? e0 : (BR3==1) ? e1 : (BR3==2) ? e2 : e3;
        conv3_body<BR3>(smem, tid, w0, h0, z3*4, b3, eta, c, &g_h2b[BR3 & 1][0]);
    }
}

// ---------------- launcher -----------------------------------------------------
extern "C" void kernel_launch(void* const* d_in, const int* in_sizes, int n_in,
                              void* d_out, int out_size){
    (void)in_sizes; (void)n_in; (void)out_size;
    const float* img  = (const float*)d_in[0];
    const float* sino = (const float*)d_in[1];
    const float* w1   = (const float*)d_in[2];
    const float* b1   = (const float*)d_in[3];
    const float* w2   = (const float*)d_in[4];
    const float* b2   = (const float*)d_in[5];
    const float* w3   = (const float*)d_in[6];
    const float* b3   = (const float*)d_in[7];
    const float* ntx  = (const float*)d_in[8];
    const float* nty  = (const float*)d_in[9];
    const float* ntz  = (const float*)d_in[10];
    const float* nt   = (const float*)d_in[11];
    float* out = (float*)d_out;

    cudaFuncSetAttribute(k_step<0,0,true,false>, cudaFuncAttributeMaxDynamicSharedMemorySize, CV12_SMEM);
    cudaFuncSetAttribute(k_step<1,0,true,true>,  cudaFuncAttributeMaxDynamicSharedMemorySize, CV12_SMEM);
    cudaFuncSetAttribute(k_step<2,1,true,true>,  cudaFuncAttributeMaxDynamicSharedMemorySize, CV12_SMEM);
    cudaFuncSetAttribute(k_step<3,2,true,true>,  cudaFuncAttributeMaxDynamicSharedMemorySize, CV12_SMEM);
    cudaFuncSetAttribute(k_step<0,3,false,true>, cudaFuncAttributeMaxDynamicSharedMemorySize, CV12_SMEM);

    dim3 gS(16, 8, 16);                 // single-op: w/8, h/16, d/4
    dim3 gM(16, 8, 32);                 // merged: conv12 z<16, conv3 z>=16
    k_init<<<NN/256, 256>>>(img, out);
    k_wprep<<<4, 256>>>(w1, w2, w3);
    k_sumz<<<HW/64, 256>>>(sino);
    for (int c = 0; c < 3; c++){
        k_step<0,0,true,false><<<gS, 256, CV12_SMEM>>>(b1, b2, b3, ntx, nty, ntz, nt, c);
        k_step<1,0,true,true> <<<gM, 256, CV12_SMEM>>>(b1, b2, b3, ntx, nty, ntz, nt, c);
        k_step<2,1,true,true> <<<gM, 256, CV12_SMEM>>>(b1, b2, b3, ntx, nty, ntz, nt, c);
        k_step<3,2,true,true> <<<gM, 256, CV12_SMEM>>>(b1, b2, b3, ntx, nty, ntz, nt, c);
        k_step<0,3,false,true><<<gS, 256, CV12_SMEM>>>(b1, b2, b3, ntx, nty, ntz, nt, c);
        k_updz<<<HW/64, 256>>>(out + (c+1)*NN, sino);
    }
}

// round 16
// speedup vs baseline: 1.0958x; 1.0958x over previous
#include <cuda_runtime.h>
#include <cstdint>

#define Dd 64
#define Hh 128
#define Ww 128
#define HW (Hh*Ww)
#define NN (Dd*Hh*Ww)

// ---------------- scratch (device globals: alloc-free, capture-safe) ----------
__device__ float g_t[NN];
__device__ float g_z[NN];
__device__ float g_p[NN];
__device__ float g_q[NN];
__device__ float g_s[NN];
__device__ float g_zp[NN];
// bf16 intermediate (h2 only; h1 lives in SMEM inside the fused kernel)
__device__ uint32_t g_h2b[8*NN];
// prepped bf16 weight fragments (constant across cascades)
__device__ uint4  g_w2f4[4*864];    // [br][tap 27][nt 2][lane 32] uint2 pairs
__device__ uint4  g_w3f4[4*432];    // [br][tap 27][lane 32] uint2 pairs
__device__ uint2  g_w1f[4*128];     // [br][lane 32][ks 2][nt 2]

// ---------------- bf16 / mma.sync helpers (family-safe PTX) ---------------------
static __device__ __forceinline__ uint32_t smem_u32(const void* p){
    uint32_t a;
    asm("{ .reg .u64 t; cvta.to.shared.u64 t, %1; cvt.u32.u64 %0, t; }" : "=r"(a) : "l"(p));
    return a;
}
static __device__ __forceinline__ uint32_t bf16x2(float lo, float hi){
    uint32_t r;
    asm("cvt.rn.bf16x2.f32 %0, %1, %2;" : "=r"(r) : "f"(hi), "f"(lo));
    return r;
}
static __device__ __forceinline__ void lds_v2(uint32_t addr, uint32_t &x, uint32_t &y){
    asm volatile("ld.shared.v2.u32 {%0,%1}, [%2];" : "=r"(x), "=r"(y) : "r"(addr));
}
static __device__ __forceinline__ float lds_f32(uint32_t addr){
    float v;
    asm volatile("ld.shared.f32 %0, [%1];" : "=f"(v) : "r"(addr));
    return v;
}
static __device__ __forceinline__ void sts_u32(uint32_t addr, uint32_t v){
    asm volatile("st.shared.u32 [%0], %1;" :: "r"(addr), "r"(v));
}
static __device__ __forceinline__ void mma_bf16(float* c, uint32_t a0, uint32_t a1,
                                                uint32_t a2, uint32_t a3,
                                                uint32_t b0, uint32_t b1){
    asm volatile(
        "mma.sync.aligned.m16n8k16.row.col.f32.bf16.bf16.f32 "
        "{%0,%1,%2,%3}, {%4,%5,%6,%7}, {%8,%9}, {%0,%1,%2,%3};"
        : "+f"(c[0]), "+f"(c[1]), "+f"(c[2]), "+f"(c[3])
        : "r"(a0), "r"(a1), "r"(a2), "r"(a3), "r"(b0), "r"(b1));
}

// x = fdiff(z, axis) on the fly (0:W, 1:H, 2:D, 3:identity)
template<int MODE>
static __device__ __forceinline__ float getx(int d, int h, int w){
    if (d < 0 || d >= Dd || h < 0 || h >= Hh || w < 0 || w >= Ww) return 0.f;
    int idx = (d*Hh + h)*Ww + w;
    if (MODE == 0) return (w < Ww-1) ? g_z[idx+1]  - g_z[idx] : 0.f;
    if (MODE == 1) return (h < Hh-1) ? g_z[idx+Ww] - g_z[idx] : 0.f;
    if (MODE == 2) return (d < Dd-1) ? g_z[idx+HW] - g_z[idx] : 0.f;
    return g_z[idx];
}

// ---------------- init ------------------------------------------------------------
__global__ void k_init(const float* __restrict__ img, float* __restrict__ outp){
    int idx = blockIdx.x*256 + threadIdx.x;
    float v = img[idx];
    g_t[idx] = v;
    outp[idx] = v;
    g_p[idx] = 0.f; g_q[idx] = 0.f; g_s[idx] = 0.f;
}

// ---------------- weight prep: f32 -> bf16 fragment layouts ----------------------
__global__ void k_wprep(const float* __restrict__ w1,
                        const float* __restrict__ w2,
                        const float* __restrict__ w3){
    const int br = blockIdx.x;
    const int tid = threadIdx.x;
    uint32_t* w2f = reinterpret_cast<uint32_t*>(g_w2f4) + br*3456;
    for (int i = tid; i < 1728; i += 256){
        int l = i & 31, nt = (i >> 5) & 1, tap = i >> 6;
        int lt = l & 3, lg = l >> 2;
        const float* wp = w2 + br*6912 + ((nt*8 + lg)*16)*27 + tap;
        uint32_t base = (uint32_t)(tap*512 + nt*256 + l*8) >> 2;
        w2f[base + 0] = bf16x2(wp[(2*lt  )*27], wp[(2*lt+1)*27]);
        w2f[base + 1] = bf16x2(wp[(2*lt+8)*27], wp[(2*lt+9)*27]);
    }
    uint32_t* w3f = reinterpret_cast<uint32_t*>(g_w3f4) + br*1728;
    for (int i = tid; i < 864; i += 256){
        int l = i & 31, tap = i >> 5;
        int lt = l & 3, lg = l >> 2;
        uint32_t v0 = 0u, v1 = 0u;
        if (lg == 0){
            const float* wp = w3 + br*432;
            v0 = bf16x2(wp[(2*lt  )*27 + tap], wp[(2*lt+1)*27 + tap]);
            v1 = bf16x2(wp[(2*lt+8)*27 + tap], wp[(2*lt+9)*27 + tap]);
        }
        uint32_t base = (uint32_t)(tap*256 + l*8) >> 2;
        w3f[base + 0] = v0;
        w3f[base + 1] = v1;
    }
    if (tid < 128){
        int l = tid & 31, ksnt = tid >> 5;
        int ks = ksnt >> 1, nt = ksnt & 1;
        int t = l & 3, g = l >> 2;
        const float* wp = w1 + br*432 + (nt*8 + g)*27;
        int k0 = ks*16 + 2*t;
        float f0 = (k0   < 27) ? wp[k0  ] : 0.f;
        float f1 = (k0+1 < 27) ? wp[k0+1] : 0.f;
        float f8 = (k0+8 < 27) ? wp[k0+8] : 0.f;
        float f9 = (k0+9 < 27) ? wp[k0+9] : 0.f;
        g_w1f[br*128 + l*4 + ks*2 + nt] = make_uint2(bf16x2(f0,f1), bf16x2(f8,f9));
    }
}

// ---------------- fused column kernels --------------------------------------------
__global__ void k_sumz(const float* __restrict__ sino){
    __shared__ float red[256];
    __shared__ float corr[64];
    const int tid = threadIdx.x;
    const int j = blockIdx.x*64 + (tid & 63);
    const int part = tid >> 6;
    const int dlo = part*16;
    float sum = 0.f;
    #pragma unroll
    for (int d = dlo; d < dlo+16; d++) sum += g_t[d*HW + j];
    red[tid] = sum;
    __syncthreads();
    if (part == 0){
        float s4 = red[tid] + red[tid+64] + red[tid+128] + red[tid+192];
        corr[tid] = (sino[j] - s4) * (1.f/64.f);
    }
    __syncthreads();
    float cv = corr[tid & 63];
    #pragma unroll
    for (int d = dlo; d < dlo+16; d++){
        int idx = d*HW + j;
        g_z[idx] = g_t[idx] + cv;
    }
}

__global__ void k_updz(float* __restrict__ outp, const float* __restrict__ sino){
    __shared__ float red[256];
    __shared__ float corr[64];
    const int tid = threadIdx.x;
    const int j = blockIdx.x*64 + (tid & 63);
    const int part = tid >> 6;
    const int dlo = part*16;
    const int w = j & (Ww-1);
    const int h = j >> 7;
    float sprev = (dlo > 0) ? g_s[(dlo-1)*HW + j] : 0.f;
    float sum = 0.f;
    #pragma unroll
    for (int d = dlo; d < dlo+16; d++){
        int idx = d*HW + j;
        float pv = g_p[idx], pm = (w > 0) ? g_p[idx-1] : 0.f;
        float fa = (w==Ww-1) ? pm : (pm - pv);
        float qv = g_q[idx], qm = (h > 0) ? g_q[idx-Ww] : 0.f;
        float fb = (h==Hh-1) ? qm : (qm - qv);
        float sv = g_s[idx];
        float fc = (d==Dd-1) ? sprev : (((d>0) ? sprev : 0.f) - sv);
        sprev = sv;
        float tn = fa + fb + fc + g_zp[idx];
        g_t[idx] = tn;
        outp[idx] = tn;
        sum += tn;
    }
    red[tid] = sum;
    __syncthreads();
    if (part == 0){
        float s4 = red[tid] + red[tid+64] + red[tid+128] + red[tid+192];
        corr[tid] = (sino[j] - s4) * (1.f/64.f);
    }
    __syncthreads();
    float cv = corr[tid & 63];
    #pragma unroll
    for (int d = dlo; d < dlo+16; d++){
        int idx = d*HW + j;
        g_z[idx] = g_t[idx] + cv;
    }
}

// ================= fused conv1+conv2 ==========================================
// SMEM (overlaid): A (h1 bf16, 108 blk x 320B) @0, then a UNION region:
//   conv1 phase: x tile (8x20x12 f32, 7680B) @34560 + row LUT (8640B) @42240
//   conv2 phase: B2 fragments (13824B) @34560  (copied AFTER conv1 phase)
// Total 50880B -> 4 CTAs/SM (launch_bounds(256,4)).
#define A_BYTES   (108*320)                // 34560
#define B2_OFF    A_BYTES                  // conv2-phase view of the union
#define XT_OFF    A_BYTES                  // conv1-phase view of the union
#define LUT_OFF   (XT_OFF + 1920*4)        // 42240
#define CV12_SMEM (LUT_OFF + 1080*8)       // 50880
#define B3_OFF    A_BYTES

template<int MODE>
__global__ void __launch_bounds__(256,4) k_conv12(const float* __restrict__ b1a,
                                                  const float* __restrict__ b2a){
    extern __shared__ char smem[];
    float* xs = reinterpret_cast<float*>(smem + XT_OFF);
    uint2* lut = reinterpret_cast<uint2*>(smem + LUT_OFF);
    const int tid = threadIdx.x;
    const int wid = tid >> 5;
    const int lane = tid & 31;
    const int t = lane & 3, g = lane >> 2;
    const int w0 = blockIdx.x*8, h0 = blockIdx.y*16, d0 = blockIdx.z*4;
    const float* b2 = b2a + MODE*16;
    const uint32_t sb_ = smem_u32(smem);
    const uint32_t xu  = sb_ + XT_OFF;

    // ---- stage x halo tile [dz 8][h 20][w 12] + row LUT (union: conv1 view) ----
    for (int i = tid; i < 1920; i += 256){
        int w = i % 12; int r = i / 12;
        int h = r % 20; int dz = r / 20;
        xs[i] = getx<MODE>(d0-2+dz, h0-2+h, w0-2+w);
    }
    for (int r = tid; r < 1080; r += 256){
        int dz = r/180, rem = r - dz*180;
        int h = rem/10, w = rem - h*10;
        int dg = d0-1+dz, hg = h0-1+h, wg = w0-1+w;
        bool in = (dg>=0) & (dg<Dd) & (hg>=0) & (hg<Hh) & (wg>=0) & (wg<Ww);
        uint32_t xoff = (uint32_t)((dz*240 + h*12 + w)*4);
        uint32_t aoff = (uint32_t)((dz*18 + h)*320 + w*32) | (in ? 1u : 0u);
        lut[r] = make_uint2(xoff, aoff);
    }
    __syncthreads();

    // ---- conv1 phase: 68 m16-tiles over 1080 halo rows -> A smem ----
    {
        uint2 B1[2][2];
        #pragma unroll
        for (int ks=0; ks<2; ks++)
            #pragma unroll
            for (int nt=0; nt<2; nt++)
                B1[ks][nt] = g_w1f[MODE*128 + lane*4 + ks*2 + nt];
        float blv[2], bhv[2];
        #pragma unroll
        for (int nt=0; nt<2; nt++){
            blv[nt] = b1a[MODE*16 + nt*8 + 2*t];
            bhv[nt] = b1a[MODE*16 + nt*8 + 2*t + 1];
        }
        uint32_t offb[8]; bool vvk[8];
        #pragma unroll
        for (int j=0; j<8; j++){
            int k = 2*t + (j&1) + ((j>>1)&1)*8 + (j>>2)*16;
            vvk[j] = (k < 27);
            int kk = vvk[j] ? k : 0;
            int dd = kk/9, rem = kk - dd*9;
            int dh = rem/3, dw = rem - dh*3;
            offb[j] = (uint32_t)((dd*240 + dh*12 + dw)*4);
        }
        #pragma unroll 1
        for (int it = 0; it < 9; it++){
            int m = wid + it*8;
            if (m >= 68) break;
            int rA = m*16 + g, rB = rA + 8;
            bool vA = rA < 1080, vB = rB < 1080;
            uint2 LA = lut[vA ? rA : 0];
            uint2 LB = lut[vB ? rB : 0];
            uint32_t aAx = xu + LA.x, aBx = xu + LB.x;
            bool inA = (LA.y & 1u), inB = (LB.y & 1u);
            uint32_t sA = sb_ + (LA.y & ~1u), sBs = sb_ + (LB.y & ~1u);
            float x0[8], x1[8];
            #pragma unroll
            for (int j=0; j<8; j++){
                x0[j] = vvk[j] ? lds_f32(aAx + offb[j]) : 0.f;
                x1[j] = vvk[j] ? lds_f32(aBx + offb[j]) : 0.f;
            }
            uint32_t a0 = bf16x2(x0[0],x0[1]), a1 = bf16x2(x1[0],x1[1]);
            uint32_t a2 = bf16x2(x0[2],x0[3]), a3 = bf16x2(x1[2],x1[3]);
            uint32_t c0 = bf16x2(x0[4],x0[5]), c1 = bf16x2(x1[4],x1[5]);
            uint32_t c2 = bf16x2(x0[6],x0[7]), c3 = bf16x2(x1[6],x1[7]);
            float acc1[2][4];
            #pragma unroll
            for (int nt=0; nt<2; nt++)
                #pragma unroll
                for (int j=0; j<4; j++) acc1[nt][j] = 0.f;
            #pragma unroll
            for (int nt=0; nt<2; nt++){
                mma_bf16(acc1[nt], a0,a1,a2,a3, B1[0][nt].x, B1[0][nt].y);
                mma_bf16(acc1[nt], c0,c1,c2,c3, B1[1][nt].x, B1[1][nt].y);
            }
            #pragma unroll
            for (int nt=0; nt<2; nt++){
                uint32_t slot = (uint32_t)((t*2 + nt)*4);
                if (vA){
                    uint32_t v = inA ? bf16x2(fmaxf(acc1[nt][0] + blv[nt], 0.f),
                                              fmaxf(acc1[nt][1] + bhv[nt], 0.f)) : 0u;
                    sts_u32(sA + slot, v);
                }
                if (vB){
                    uint32_t v = inB ? bf16x2(fmaxf(acc1[nt][2] + blv[nt], 0.f),
                                              fmaxf(acc1[nt][3] + bhv[nt], 0.f)) : 0u;
                    sts_u32(sBs + slot, v);
                }
            }
        }
    }
    __syncthreads();

    // ---- B2 fragment copy into the union region (conv2 view) ----
    {
        const uint4* wsrc = g_w2f4 + MODE*864;
        uint4* wdst = reinterpret_cast<uint4*>(smem + B2_OFF);
        for (int i = tid; i < 864; i += 256) wdst[i] = wsrc[i];
    }
    __syncthreads();

    // ---- conv2 mainloop ----
    float acc[4][8];
    #pragma unroll
    for (int s=0; s<4; s++)
        #pragma unroll
        for (int j=0; j<8; j++) acc[s][j] = 0.f;

    const uint32_t a_base = sb_ + (uint32_t)(2*wid)*320u + (uint32_t)g*32u + (uint32_t)t*8u;
    const uint32_t b_base = sb_ + B2_OFF + (uint32_t)lane*8u;

    #pragma unroll 1
    for (int dh = 0; dh < 3; dh++){
        #pragma unroll
        for (int dw = 0; dw < 3; dw++){
            uint32_t bf[3][2][2];
            #pragma unroll
            for (int dd=0; dd<3; dd++)
                #pragma unroll
                for (int nt=0; nt<2; nt++)
                    lds_v2(b_base + (uint32_t)(dd*9+dh*3+dw)*512u + nt*256u,
                           bf[dd][nt][0], bf[dd][nt][1]);
            uint32_t ab = a_base + (uint32_t)dh*320u + (uint32_t)dw*32u;
            #pragma unroll
            for (int dblk=0; dblk<6; dblk++){
                uint32_t a0,a2,a1,a3;
                lds_v2(ab + (uint32_t)dblk*5760u,        a0, a2);
                lds_v2(ab + (uint32_t)dblk*5760u + 320u, a1, a3);
                #pragma unroll
                for (int dd=0; dd<3; dd++){
                    const int s = dblk - dd;
                    if (s >= 0 && s < 4){
                        mma_bf16(&acc[s][0], a0,a1,a2,a3, bf[dd][0][0], bf[dd][0][1]);
                        mma_bf16(&acc[s][4], a0,a1,a2,a3, bf[dd][1][0], bf[dd][1][1]);
                    }
                }
            }
        }
    }

    #pragma unroll
    for (int nt = 0; nt < 2; nt++){
        float blv = b2[nt*8 + 2*t], bhv = b2[nt*8 + 2*t + 1];
        #pragma unroll
        for (int s = 0; s < 4; s++){
            int pos0 = ((d0+s)*Hh + h0 + 2*wid)*Ww + w0 + g;
            uint32_t v0 = bf16x2(fmaxf(acc[s][nt*4+0] + blv, 0.f),
                                 fmaxf(acc[s][nt*4+1] + bhv, 0.f));
            uint32_t v1 = bf16x2(fmaxf(acc[s][nt*4+2] + blv, 0.f),
                                 fmaxf(acc[s][nt*4+3] + bhv, 0.f));
            g_h2b[ pos0     *8 + t*2 + nt] = v0;
            g_h2b[(pos0+Ww) *8 + t*2 + nt] = v1;
        }
    }
}

// ================= conv3: 16 -> 1 via mma.sync bf16, fused updates =============
static __device__ __forceinline__ void stage_A(char* smem, const uint32_t* src,
                                               int tid, int w0, int h0, int d0){
    for (int i = tid; i < 2160; i += 256){
        int half = i & 1;
        int w = (i >> 1) % 10;
        int b = i / 20;
        int d = d0 - 1 + b/18;
        int h = h0 - 1 + b%18;
        int wg = w0 - 1 + w;
        uint4 v = make_uint4(0u,0u,0u,0u);
        if (d >= 0 && d < Dd && h >= 0 && h < Hh && wg >= 0 && wg < Ww)
            v = *reinterpret_cast<const uint4*>(src + (((d*Hh + h)*Ww + wg)*8 + half*4));
        *reinterpret_cast<uint4*>(smem + b*320 + w*32 + half*16) = v;
    }
}

#define CV3_SMEM (B3_OFF + 27*256)         // 41472

template<int A>
__global__ void __launch_bounds__(256,4) k_conv3m(const float* __restrict__ b3,
                                                  const float* __restrict__ eta_arr,
                                                  int c){
    extern __shared__ char smem[];
    const int tid = threadIdx.x;
    const int wid = tid >> 5;
    const int lane = tid & 31;
    const int t = lane & 3, g = lane >> 2;
    const int w0 = blockIdx.x*8, h0 = blockIdx.y*16, d0 = blockIdx.z*4;

    stage_A(smem, g_h2b, tid, w0, h0, d0);
    {
        const uint4* wsrc = g_w3f4 + A*432;
        uint4* wdst = reinterpret_cast<uint4*>(smem + B3_OFF);
        for (int i = tid; i < 432; i += 256) wdst[i] = wsrc[i];
    }
    __syncthreads();

    float acc[4][4];
    #pragma unroll
    for (int s=0; s<4; s++)
        #pragma unroll
        for (int j=0; j<4; j++) acc[s][j] = 0.f;

    const uint32_t sb_ = smem_u32(smem);
    const uint32_t a_base = sb_ + (uint32_t)(2*wid)*320u + (uint32_t)g*32u + (uint32_t)t*8u;
    const uint32_t b_base = sb_ + B3_OFF + (uint32_t)lane*8u;

    #pragma unroll 1
    for (int dh = 0; dh < 3; dh++){
        #pragma unroll
        for (int dw = 0; dw < 3; dw++){
            uint32_t bf[3][2];
            #pragma unroll
            for (int dd=0; dd<3; dd++)
                lds_v2(b_base + (uint32_t)(dd*9+dh*3+dw)*256u, bf[dd][0], bf[dd][1]);
            uint32_t ab = a_base + (uint32_t)dh*320u + (uint32_t)dw*32u;
            #pragma unroll
            for (int dblk=0; dblk<6; dblk++){
                uint32_t a0,a2,a1,a3;
                lds_v2(ab + (uint32_t)dblk*5760u,        a0, a2);
                lds_v2(ab + (uint32_t)dblk*5760u + 320u, a1, a3);
                #pragma unroll
                for (int dd=0; dd<3; dd++){
                    const int s = dblk - dd;
                    if (s >= 0 && s < 4)
                        mma_bf16(&acc[s][0], a0,a1,a2,a3, bf[dd][0], bf[dd][1]);
                }
            }
        }
    }

    if (t == 0){
        float* tgt        = (A==0) ? g_p : (A==1) ? g_q : (A==2) ? g_s : g_zp;
        const float* base = (A==3) ? g_t : tgt;
        const float eta = eta_arr[c];
        const float b3v = b3[A];
        #pragma unroll
        for (int s = 0; s < 4; s++){
            #pragma unroll
            for (int hl = 0; hl < 2; hl++){
                int d = d0 + s, h = h0 + 2*wid + hl, w = w0 + g;
                int idx = (d*Hh + h)*Ww + w;
                float nnew = getx<A>(d, h, w) + acc[s][hl*2] + b3v;
                tgt[idx] = (1.f + eta)*base[idx] - eta*nnew;
            }
        }
    }
}

// ---------------- launcher -----------------------------------------------------
extern "C" void kernel_launch(void* const* d_in, const int* in_sizes, int n_in,
                              void* d_out, int out_size){
    (void)in_sizes; (void)n_in; (void)out_size;
    const float* img  = (const float*)d_in[0];
    const float* sino = (const float*)d_in[1];
    const float* w1   = (const float*)d_in[2];
    const float* b1   = (const float*)d_in[3];
    const float* w2   = (const float*)d_in[4];
    const float* b2   = (const float*)d_in[5];
    const float* w3   = (const float*)d_in[6];
    const float* b3   = (const float*)d_in[7];
    const float* ntx  = (const float*)d_in[8];
    const float* nty  = (const float*)d_in[9];
    const float* ntz  = (const float*)d_in[10];
    const float* nt   = (const float*)d_in[11];
    float* out = (float*)d_out;

    cudaFuncSetAttribute(k_conv12<0>, cudaFuncAttributeMaxDynamicSharedMemorySize, CV12_SMEM);
    cudaFuncSetAttribute(k_conv12<1>, cudaFuncAttributeMaxDynamicSharedMemorySize, CV12_SMEM);
    cudaFuncSetAttribute(k_conv12<2>, cudaFuncAttributeMaxDynamicSharedMemorySize, CV12_SMEM);
    cudaFuncSetAttribute(k_conv12<3>, cudaFuncAttributeMaxDynamicSharedMemorySize, CV12_SMEM);

    dim3 g2(16, 8, 16);                 // w/8, h/16, d/4
    k_init<<<NN/256, 256>>>(img, out);
    k_wprep<<<4, 256>>>(w1, w2, w3);
    k_sumz<<<HW/64, 256>>>(sino);
    for (int c = 0; c < 3; c++){
        k_conv12<0><<<g2, 256, CV12_SMEM>>>(b1, b2);
        k_conv3m<0><<<g2, 256, CV3_SMEM>>>(b3, ntx, c);

        k_conv12<1><<<g2, 256, CV12_SMEM>>>(b1, b2);
        k_conv3m<1><<<g2, 256, CV3_SMEM>>>(b3, nty, c);

        k_conv12<2><<<g2, 256, CV12_SMEM>>>(b1, b2);
        k_conv3m<2><<<g2, 256, CV3_SMEM>>>(b3, ntz, c);

        k_conv12<3><<<g2, 256, CV12_SMEM>>>(b1, b2);
        k_conv3m<3><<<g2, 256, CV3_SMEM>>>(b3, nt, c);

        k_updz<<<HW/64, 256>>>(out + (c+1)*NN, sino);
    }
}